// round 8
// baseline (speedup 1.0000x reference)
#include <cuda_runtime.h>
#include <cuda_fp16.h>

// CostVolumeManager: plane-sweep cost volume. B=1, S=8, C=16, H=64, W=96, D=64.
//
// v5: kill exposed L2 latency + ALU overhead.
//   - source fp16 features in TWO zero-PADDED planes (16B/pixel, 2-px apron).
//     Pads are never written; __device__ globals are zero-initialized, so
//     grid_sample zeros-padding falls out of the data -> no clamps/selects.
//   - block covers 32 depths x 32 x at one y (4 depths/thread): the block's
//     epipolar band (~50-100KB) is reused across 32 depths -> L1-resident,
//     gathers become L1 hits instead of ~250-cycle L2 hits.
//   - taps addressed as [p], [p+1], [p+Wp], [p+Wp+1]: one IMAD per (d,s),
//     LDG immediate offsets.
//   - rolled source loop (I$-friendly), unrolled 4-depth body sharing P·ray.

namespace cvk {

constexpr int S = 8, C = 16, H = 64, W = 96, D = 64, N = H * W;
constexpr int Wp = W + 4, Hp = H + 4;          // 2-pixel zero apron each side
constexpr int NP = Hp * Wp;                    // 6800 padded pixels
constexpr int SRC_PACK_BLOCKS = (S * N * 4) / 256;   // 768
constexpr int CUR_PACK_BLOCKS = (N * 4) / 256;       // 96

typedef unsigned long long ull;

// Static device scratch (zero-initialized at module load; pads never written).
__device__ uint4  g_srcA[S * NP];   // fp16 ch0..7  per padded pixel
__device__ uint4  g_srcB[S * NP];   // fp16 ch8..15 per padded pixel
__device__ float4 g_cur[4 * N];     // fp32 cur feats, plane q = ch 4q..4q+3

// ---------------------------------------------------------------- pack pass
__global__ __launch_bounds__(256)
void pack_all(const float* __restrict__ src, const float* __restrict__ cur) {
    int bid = blockIdx.x;
    if (bid < SRC_PACK_BLOCKS) {
        int idx = bid * 256 + threadIdx.x;        // h*(S*N) + s*N + n
        int h = idx / (S * N);                    // 4-channel group 0..3
        int sn = idx - h * (S * N);
        int n_local = sn % N;
        int s = sn / N;
        int y = n_local / W, x = n_local - y * W;
        const float* p = src + (size_t)s * C * N + (size_t)(4 * h) * N + n_local;
        __half2 a = __floats2half2_rn(p[0],     p[N]);
        __half2 b = __floats2half2_rn(p[2 * N], p[3 * N]);
        uint2 v;
        v.x = *reinterpret_cast<unsigned*>(&a);
        v.y = *reinterpret_cast<unsigned*>(&b);
        int pp = (s * Hp + y + 2) * Wp + (x + 2); // padded pixel index
        uint2* plane = (h < 2) ? reinterpret_cast<uint2*>(g_srcA)
                               : reinterpret_cast<uint2*>(g_srcB);
        plane[(size_t)pp * 2 + (h & 1)] = v;
    } else {
        int idx = (bid - SRC_PACK_BLOCKS) * 256 + threadIdx.x;  // q*N + n
        int q = idx / N;
        int n = idx - q * N;
        float4 f;
        f.x = cur[(size_t)(4 * q + 0) * N + n];
        f.y = cur[(size_t)(4 * q + 1) * N + n];
        f.z = cur[(size_t)(4 * q + 2) * N + n];
        f.w = cur[(size_t)(4 * q + 3) * N + n];
        g_cur[idx] = f;
    }
}

// ------------------------------------------------------------ packed helpers
__device__ __forceinline__ ull pack_f2(float lo, float hi) {
    ull u;
    asm("mov.b64 %0, {%1, %2};" : "=l"(u) : "f"(lo), "f"(hi));
    return u;
}
__device__ __forceinline__ void unpack_f2(ull u, float& lo, float& hi) {
    asm("mov.b64 {%0, %1}, %2;" : "=f"(lo), "=f"(hi) : "l"(u));
}
__device__ __forceinline__ void fma_f32x2(ull& d, ull a, ull b) {
    asm("fma.rn.f32x2 %0, %1, %2, %3;" : "=l"(d) : "l"(a), "l"(b), "l"(d));
}

// Blend 4 taps (one 16B plane = 4 half2) with fp16 weights, dot against
// packed fp32 cur pairs, accumulating into acc (f32x2).
__device__ __forceinline__ void blend_dot(ull& acc,
                                          uint4 t00, uint4 t10, uint4 t01, uint4 t11,
                                          __half2 h00, __half2 h10,
                                          __half2 h01, __half2 h11,
                                          const ull* __restrict__ cfp) {
#pragma unroll
    for (int j = 0; j < 4; j++) {
        __half2 a = *(reinterpret_cast<__half2*>(&t00.x) + j);
        __half2 b = *(reinterpret_cast<__half2*>(&t10.x) + j);
        __half2 c = *(reinterpret_cast<__half2*>(&t01.x) + j);
        __half2 e = *(reinterpret_cast<__half2*>(&t11.x) + j);
        __half2 v = __hmul2(a, h00);
        v = __hfma2(b, h10, v);
        v = __hfma2(c, h01, v);
        v = __hfma2(e, h11, v);
        float2 f = __half22float2(v);
        fma_f32x2(acc, pack_f2(f.x, f.y), cfp[j]);
    }
}

// One depth through one source. No clamps, no validity selects: padded data.
__device__ __forceinline__ void proc_depth(ull& acc, float dep,
                                           float au, float av, float az,
                                           float bu, float bv, float bz,
                                           int sbase,
                                           const ull* __restrict__ cfp) {
    float pu = dep * au + bu;
    float pv = dep * av + bv;
    float pz = dep * az + bz;
    float iz = 1.f / (pz + 1e-8f);
    float gx = pu * iz - 0.5f;
    float gy = pv * iz - 0.5f;
    // Clamp into the apron: any fully-OOB coordinate reads zero pixels.
    // fmaxf(NaN, c) = c -> NaN-safe.
    gx = fminf(fmaxf(gx, -1.5f), (float)W + 0.5f);
    gy = fminf(fmaxf(gy, -1.5f), (float)H + 0.5f);
    float x0f = floorf(gx), y0f = floorf(gy);
    float wx = gx - x0f, wy = gy - y0f;
    int x0 = (int)x0f, y0 = (int)y0f;

    float zm  = (pz > 0.f) ? 1.f : 0.f;        // mask = z > 0
    float wy0 = zm * (1.f - wy);
    float wy1 = zm * wy;
    float wx0 = 1.f - wx;
    __half2 h00 = __float2half2_rn(wx0 * wy0);
    __half2 h10 = __float2half2_rn(wx  * wy0);
    __half2 h01 = __float2half2_rn(wx0 * wy1);
    __half2 h11 = __float2half2_rn(wx  * wy1);

    int pp = sbase + (y0 + 2) * Wp + (x0 + 2); // single address; taps at imm offsets
    const uint4* A = g_srcA + pp;
    const uint4* Bp = g_srcB + pp;
    uint4 a00 = A[0],  a10 = A[1],  a01 = A[Wp],  a11 = A[Wp + 1];
    uint4 b00 = Bp[0], b10 = Bp[1], b01 = Bp[Wp], b11 = Bp[Wp + 1];

    blend_dot(acc, a00, a10, a01, a11, h00, h10, h01, h11, cfp + 0);
    blend_dot(acc, b00, b10, b01, b11, h00, h10, h01, h11, cfp + 4);
}

// --------------------------------------------------------------- main kernel
__global__ __launch_bounds__(256, 2)
void cost_main(const float* __restrict__ exts, const float* __restrict__ Ks,
               const float* __restrict__ invK, const float* __restrict__ mnp,
               const float* __restrict__ mxp, float* __restrict__ out) {
    __shared__ float sP[S][12];
    int t = threadIdx.y * 32 + threadIdx.x;
    if (t < S * 12) {
        int s = t / 12, rc = t - 12 * s, r = rc >> 2, c = rc & 3;
        float accm = 0.f;
#pragma unroll
        for (int k = 0; k < 4; k++)
            accm += Ks[s * 16 + r * 4 + k] * exts[s * 16 + k * 4 + c];
        sP[s][rc] = accm;
    }
    __syncthreads();

    int x = blockIdx.x * 32 + threadIdx.x;
    int y = blockIdx.y;
    int d0 = blockIdx.z * 32 + threadIdx.y * 4;   // this thread: d0..d0+3
    int n = y * W + x;

    // Geometric depth bins
    float mnv = mnp[0], mxv = mxp[0];
    float lstep = logf(mxv / mnv) * (1.f / 63.f);
    float r = expf(lstep);
    float dep[4];
    dep[0] = expf(logf(mnv) + lstep * (float)d0);
    dep[1] = dep[0] * r;
    dep[2] = dep[1] * r;
    dep[3] = dep[2] * r;

    // Unit-depth back-projected ray
    float pxc = (float)x + 0.5f, pyc = (float)y + 0.5f;
    float rx = invK[0] * pxc + invK[1] * pyc + invK[2];
    float ry = invK[4] * pxc + invK[5] * pyc + invK[6];
    float rz = invK[8] * pxc + invK[9] * pyc + invK[10];

    // Current-frame features as 8 packed f32x2 pairs (shared by all 4 depths).
    ull cfp[8];
#pragma unroll
    for (int q = 0; q < 4; q++) {
        float4 f = g_cur[q * N + n];
        cfp[2 * q + 0] = pack_f2(f.x, f.y);
        cfp[2 * q + 1] = pack_f2(f.z, f.w);
    }

    ull acc[4] = {0ull, 0ull, 0ull, 0ull};

#pragma unroll 1                                 // rolled: keep body in L0 I$
    for (int s = 0; s < S; s++) {
        const float* P = sP[s];
        float au = P[0] * rx + P[1] * ry + P[2]  * rz;
        float av = P[4] * rx + P[5] * ry + P[6]  * rz;
        float az = P[8] * rx + P[9] * ry + P[10] * rz;
        float bu = P[3], bv = P[7], bz = P[11];
        int sbase = s * NP;
#pragma unroll
        for (int k = 0; k < 4; k++)
            proc_depth(acc[k], dep[k], au, av, az, bu, bv, bz, sbase, cfp);
    }

#pragma unroll
    for (int k = 0; k < 4; k++) {
        float lo, hi;
        unpack_f2(acc[k], lo, hi);
        out[(d0 + k) * N + n] = lo + hi;          // cost_volume
        out[D * N + (d0 + k) * N + n] = dep[k];   // depth_planes
    }
}

}  // namespace cvk

extern "C" void kernel_launch(void* const* d_in, const int* in_sizes, int n_in,
                              void* d_out, int out_size) {
    using namespace cvk;
    const float* cur  = (const float*)d_in[0];  // [1,16,64,96]
    const float* src  = (const float*)d_in[1];  // [1,8,16,64,96]
    const float* exts = (const float*)d_in[2];  // [1,8,4,4]
    const float* Ks   = (const float*)d_in[3];  // [1,8,4,4]
    const float* invK = (const float*)d_in[4];  // [1,4,4]
    const float* mnp  = (const float*)d_in[5];  // [1,1,1,1]
    const float* mxp  = (const float*)d_in[6];  // [1,1,1,1]
    float* out = (float*)d_out;

    pack_all<<<SRC_PACK_BLOCKS + CUR_PACK_BLOCKS, 256>>>(src, cur);

    dim3 blk(32, 8);
    dim3 grd(W / 32, H, D / 32);   // 4 depths/thread, 32 depths/block
    cost_main<<<grd, blk>>>(exts, Ks, invK, mnp, mxp, out);
}

// round 10
// speedup vs baseline: 1.3337x; 1.3337x over previous
#include <cuda_runtime.h>
#include <cuda_fp16.h>

// CostVolumeManager: plane-sweep cost volume. B=1, S=8, C=16, H=64, W=96, D=64.
//
// v6: L1 wavefront reduction via 2D lane tiling.
//   Diagnosis: cost_main invariant at ~28.7us across occ 21-42% => pinned by
//   L1tex wavefront replays (each 32-lane-x LDG spans ~5 lines). Remap each
//   warp to an 8x * 4d tile: 8 x-lanes span 128B (2 lines); the 4 depth
//   groups sample nearly identical epipolar positions -> lines shared.
//   Keep: zero-padded fp16 planes (branchless taps, single address + imm
//   offsets), 16B channel-split granule, HFMA2 blend + f32x2 dot.
//   Grid back to 1536 blocks (round-8's 384 blocks = 1.3 waves -> tail).

namespace cvk {

constexpr int S = 8, C = 16, H = 64, W = 96, D = 64, N = H * W;
constexpr int Wp = W + 4, Hp = H + 4;          // 2-pixel zero apron each side
constexpr int NP = Hp * Wp;
constexpr int SRC_PACK_BLOCKS = (S * N * 4) / 256;   // 768
constexpr int CUR_PACK_BLOCKS = (N * 4) / 256;       // 96

typedef unsigned long long ull;

// Static device scratch (zero-initialized at module load; pads never written).
__device__ uint4  g_srcA[S * NP];   // fp16 ch0..7  per padded pixel
__device__ uint4  g_srcB[S * NP];   // fp16 ch8..15 per padded pixel
__device__ float4 g_cur[4 * N];     // fp32 cur feats, plane q = ch 4q..4q+3

// ---------------------------------------------------------------- pack pass
__global__ __launch_bounds__(256)
void pack_all(const float* __restrict__ src, const float* __restrict__ cur) {
    int bid = blockIdx.x;
    if (bid < SRC_PACK_BLOCKS) {
        int idx = bid * 256 + threadIdx.x;        // h*(S*N) + s*N + n
        int h = idx / (S * N);                    // 4-channel group 0..3
        int sn = idx - h * (S * N);
        int n_local = sn % N;
        int s = sn / N;
        int y = n_local / W, x = n_local - y * W;
        const float* p = src + (size_t)s * C * N + (size_t)(4 * h) * N + n_local;
        __half2 a = __floats2half2_rn(p[0],     p[N]);
        __half2 b = __floats2half2_rn(p[2 * N], p[3 * N]);
        uint2 v;
        v.x = *reinterpret_cast<unsigned*>(&a);
        v.y = *reinterpret_cast<unsigned*>(&b);
        int pp = (s * Hp + y + 2) * Wp + (x + 2); // padded pixel index
        uint2* plane = (h < 2) ? reinterpret_cast<uint2*>(g_srcA)
                               : reinterpret_cast<uint2*>(g_srcB);
        plane[(size_t)pp * 2 + (h & 1)] = v;
    } else {
        int idx = (bid - SRC_PACK_BLOCKS) * 256 + threadIdx.x;  // q*N + n
        int q = idx / N;
        int n = idx - q * N;
        float4 f;
        f.x = cur[(size_t)(4 * q + 0) * N + n];
        f.y = cur[(size_t)(4 * q + 1) * N + n];
        f.z = cur[(size_t)(4 * q + 2) * N + n];
        f.w = cur[(size_t)(4 * q + 3) * N + n];
        g_cur[idx] = f;
    }
}

// ------------------------------------------------------------ packed helpers
__device__ __forceinline__ ull pack_f2(float lo, float hi) {
    ull u;
    asm("mov.b64 %0, {%1, %2};" : "=l"(u) : "f"(lo), "f"(hi));
    return u;
}
__device__ __forceinline__ void unpack_f2(ull u, float& lo, float& hi) {
    asm("mov.b64 {%0, %1}, %2;" : "=f"(lo), "=f"(hi) : "l"(u));
}
__device__ __forceinline__ void fma_f32x2(ull& d, ull a, ull b) {
    asm("fma.rn.f32x2 %0, %1, %2, %3;" : "=l"(d) : "l"(a), "l"(b), "l"(d));
}

// Blend 4 taps (one 16B plane = 4 half2) with fp16 weights, dot against
// packed fp32 cur pairs, accumulating into acc (f32x2).
__device__ __forceinline__ void blend_dot(ull& acc,
                                          uint4 t00, uint4 t10, uint4 t01, uint4 t11,
                                          __half2 h00, __half2 h10,
                                          __half2 h01, __half2 h11,
                                          const ull* __restrict__ cfp) {
#pragma unroll
    for (int j = 0; j < 4; j++) {
        __half2 a = *(reinterpret_cast<__half2*>(&t00.x) + j);
        __half2 b = *(reinterpret_cast<__half2*>(&t10.x) + j);
        __half2 c = *(reinterpret_cast<__half2*>(&t01.x) + j);
        __half2 e = *(reinterpret_cast<__half2*>(&t11.x) + j);
        __half2 v = __hmul2(a, h00);
        v = __hfma2(b, h10, v);
        v = __hfma2(c, h01, v);
        v = __hfma2(e, h11, v);
        float2 f = __half22float2(v);
        fma_f32x2(acc, pack_f2(f.x, f.y), cfp[j]);
    }
}

// One depth through one source. No clamps, no validity selects: padded data.
__device__ __forceinline__ void proc_depth(ull& acc, float dep,
                                           float au, float av, float az,
                                           float bu, float bv, float bz,
                                           int sbase,
                                           const ull* __restrict__ cfp) {
    float pu = dep * au + bu;
    float pv = dep * av + bv;
    float pz = dep * az + bz;
    float iz = 1.f / (pz + 1e-8f);
    float gx = pu * iz - 0.5f;
    float gy = pv * iz - 0.5f;
    // Clamp into the apron: any fully-OOB coordinate reads zero pixels.
    // fmaxf(NaN, c) = c -> NaN-safe.
    gx = fminf(fmaxf(gx, -1.5f), (float)W + 0.5f);
    gy = fminf(fmaxf(gy, -1.5f), (float)H + 0.5f);
    float x0f = floorf(gx), y0f = floorf(gy);
    float wx = gx - x0f, wy = gy - y0f;
    int x0 = (int)x0f, y0 = (int)y0f;

    float zm  = (pz > 0.f) ? 1.f : 0.f;        // mask = z > 0
    float wy0 = zm * (1.f - wy);
    float wy1 = zm * wy;
    float wx0 = 1.f - wx;
    __half2 h00 = __float2half2_rn(wx0 * wy0);
    __half2 h10 = __float2half2_rn(wx  * wy0);
    __half2 h01 = __float2half2_rn(wx0 * wy1);
    __half2 h11 = __float2half2_rn(wx  * wy1);

    int pp = sbase + (y0 + 2) * Wp + (x0 + 2); // single address; imm-offset taps
    const uint4* A  = g_srcA + pp;
    const uint4* Bp = g_srcB + pp;
    uint4 a00 = A[0],  a10 = A[1],  a01 = A[Wp],  a11 = A[Wp + 1];
    uint4 b00 = Bp[0], b10 = Bp[1], b01 = Bp[Wp], b11 = Bp[Wp + 1];

    blend_dot(acc, a00, a10, a01, a11, h00, h10, h01, h11, cfp + 0);
    blend_dot(acc, b00, b10, b01, b11, h00, h10, h01, h11, cfp + 4);
}

// --------------------------------------------------------------- main kernel
// Warp lane tile: 8 x  *  4 d.  Block: 8 warps = (4 x-tiles)*(2 d-tiles)
//   -> block covers 32 x * 8 d at one y.  Grid (3, 64, 8) = 1536 blocks.
__global__ __launch_bounds__(256)
void cost_main(const float* __restrict__ exts, const float* __restrict__ Ks,
               const float* __restrict__ invK, const float* __restrict__ mnp,
               const float* __restrict__ mxp, float* __restrict__ out) {
    __shared__ float sP[S][12];
    int t = threadIdx.y * 32 + threadIdx.x;
    if (t < S * 12) {
        int s = t / 12, rc = t - 12 * s, r = rc >> 2, c = rc & 3;
        float accm = 0.f;
#pragma unroll
        for (int k = 0; k < 4; k++)
            accm += Ks[s * 16 + r * 4 + k] * exts[s * 16 + k * 4 + c];
        sP[s][rc] = accm;
    }
    __syncthreads();

    int lane = threadIdx.x;
    int xloc = lane & 7;            // 0..7   within-warp x
    int dloc = lane >> 3;           // 0..3   within-warp depth
    int wx   = threadIdx.y & 3;     // 0..3   warp x-tile
    int wd   = threadIdx.y >> 2;    // 0..1   warp d-tile

    int x = blockIdx.x * 32 + wx * 8 + xloc;
    int y = blockIdx.y;
    int d = blockIdx.z * 8 + wd * 4 + dloc;
    int n = y * W + x;

    // Log-spaced depth bin (linspace(0,1,64) ramp = d/63)
    float mnv = mnp[0], mxv = mxp[0];
    float lstep = logf(mxv / mnv) * (1.f / 63.f);
    float dep = expf(logf(mnv) + lstep * (float)d);

    // Unit-depth back-projected ray
    float pxc = (float)x + 0.5f, pyc = (float)y + 0.5f;
    float rx = invK[0] * pxc + invK[1] * pyc + invK[2];
    float ry = invK[4] * pxc + invK[5] * pyc + invK[6];
    float rz = invK[8] * pxc + invK[9] * pyc + invK[10];

    // Current-frame features as 8 packed f32x2 pairs.
    ull cfp[8];
#pragma unroll
    for (int q = 0; q < 4; q++) {
        float4 f = g_cur[q * N + n];
        cfp[2 * q + 0] = pack_f2(f.x, f.y);
        cfp[2 * q + 1] = pack_f2(f.z, f.w);
    }

    ull acc = 0ull;

#pragma unroll
    for (int s = 0; s < S; s++) {
        const float* P = sP[s];
        float au = P[0] * rx + P[1] * ry + P[2]  * rz;
        float av = P[4] * rx + P[5] * ry + P[6]  * rz;
        float az = P[8] * rx + P[9] * ry + P[10] * rz;
        proc_depth(acc, dep, au, av, az, P[3], P[7], P[11], s * NP, cfp);
    }

    float lo, hi;
    unpack_f2(acc, lo, hi);
    out[d * N + n] = lo + hi;            // cost_volume [D,H,W]
    out[D * N + d * N + n] = dep;        // depth_planes [D,H,W]
}

}  // namespace cvk

extern "C" void kernel_launch(void* const* d_in, const int* in_sizes, int n_in,
                              void* d_out, int out_size) {
    using namespace cvk;
    const float* cur  = (const float*)d_in[0];  // [1,16,64,96]
    const float* src  = (const float*)d_in[1];  // [1,8,16,64,96]
    const float* exts = (const float*)d_in[2];  // [1,8,4,4]
    const float* Ks   = (const float*)d_in[3];  // [1,8,4,4]
    const float* invK = (const float*)d_in[4];  // [1,4,4]
    const float* mnp  = (const float*)d_in[5];  // [1,1,1,1]
    const float* mxp  = (const float*)d_in[6];  // [1,1,1,1]
    float* out = (float*)d_out;

    pack_all<<<SRC_PACK_BLOCKS + CUR_PACK_BLOCKS, 256>>>(src, cur);

    dim3 blk(32, 8);
    dim3 grd(W / 32, H, D / 8);   // 1536 blocks: full waves
    cost_main<<<grd, blk>>>(exts, Ks, invK, mnp, mxp, out);
}